// round 1
// baseline (speedup 1.0000x reference)
#include <cuda_runtime.h>
#include <math.h>

#define BATCH 4
#define CIN   64
#define HH    160
#define WW    160
#define GRP   8
#define KK    9
#define CG    8
#define NOFF  216
#define HW    (HH*WW)

// scratch: dy, dx, mask each [B][G*KK][H][W]
#define SCR_N (BATCH*GRP*KK*HH*WW)   // 7,372,800
__device__ float g_scr[3*SCR_N];

// ---------------------------------------------------------------------------
// Kernel A: 3x3 conv(feat, w_off) + b_off  -> dy / dx / sigmoid(mask) scratch
// ---------------------------------------------------------------------------
#define ATW 32
#define ATH 8
#define CI_CHUNK 8
#define CO_CHUNK 24   // 216 / 24 = 9 chunks

__global__ __launch_bounds__(256)
void offset_conv_kernel(const float* __restrict__ feat,
                        const float* __restrict__ w_off,
                        const float* __restrict__ b_off)
{
    __shared__ float sft[CI_CHUNK][ATH+2][ATW+2];
    __shared__ float swt[CI_CHUNK*9*CO_CHUNK];   // [ci][kk][co], co contiguous

    const int tx = threadIdx.x & 31;
    const int ty = threadIdx.x >> 5;
    const int bz = blockIdx.z;
    const int b = bz / 9;
    const int chunk = bz % 9;
    const int co_base = chunk * CO_CHUNK;
    const int x = blockIdx.x * ATW + tx;
    const int y = blockIdx.y * ATH + ty;

    float acc[CO_CHUNK];
#pragma unroll
    for (int i = 0; i < CO_CHUNK; i++) acc[i] = 0.f;

    const float* fb = feat + (size_t)b * CIN * HW;

    for (int ci0 = 0; ci0 < CIN; ci0 += CI_CHUNK) {
        __syncthreads();
        // stage feat tile (with 1-pixel halo)
        for (int idx = threadIdx.x; idx < CI_CHUNK*(ATH+2)*(ATW+2); idx += 256) {
            int ci  = idx / ((ATH+2)*(ATW+2));
            int rem = idx % ((ATH+2)*(ATW+2));
            int yy = rem / (ATW+2), xx = rem % (ATW+2);
            int gy = blockIdx.y * ATH + yy - 1;
            int gx = blockIdx.x * ATW + xx - 1;
            float v = 0.f;
            if (gy >= 0 && gy < HH && gx >= 0 && gx < WW)
                v = fb[(size_t)(ci0+ci)*HW + gy*WW + gx];
            sft[ci][yy][xx] = v;
        }
        // stage transposed weights
        for (int idx = threadIdx.x; idx < CI_CHUNK*9*CO_CHUNK; idx += 256) {
            int co = idx % CO_CHUNK;
            int r  = idx / CO_CHUNK;     // ci*9 + kk
            int ci = r / 9, kk = r % 9;
            swt[idx] = w_off[((size_t)(co_base+co)*CIN + (ci0+ci))*9 + kk];
        }
        __syncthreads();

#pragma unroll
        for (int ci = 0; ci < CI_CHUNK; ci++) {
            float p[9];
#pragma unroll
            for (int j = 0; j < 9; j++)
                p[j] = sft[ci][ty + j/3][tx + j%3];
#pragma unroll
            for (int kk = 0; kk < 9; kk++) {
                const float4* w4 = (const float4*)&swt[(ci*9+kk)*CO_CHUNK];
                float pv = p[kk];
#pragma unroll
                for (int q = 0; q < CO_CHUNK/4; q++) {
                    float4 w = w4[q];
                    acc[4*q+0] += w.x * pv;
                    acc[4*q+1] += w.y * pv;
                    acc[4*q+2] += w.z * pv;
                    acc[4*q+3] += w.w * pv;
                }
            }
        }
    }

    // scatter to dy/dx/mask scratch
#pragma unroll
    for (int i = 0; i < CO_CHUNK; i++) {
        int co = co_base + i;
        float v = acc[i] + b_off[co];
        if (co < 144) {
            int g = co / 18, r = co % 18, k = r >> 1;
            float* dst = (r & 1) ? (g_scr + SCR_N) : g_scr;  // dx : dy
            dst[((b*GRP*KK + g*KK + k)*HH + y)*WW + x] = v;
        } else {
            int cm = co - 144, g = cm / 9, k = cm % 9;
            g_scr[2*SCR_N + ((b*GRP*KK + g*KK + k)*HH + y)*WW + x] =
                1.f / (1.f + expf(-v));
        }
    }
}

// ---------------------------------------------------------------------------
// Kernel B: modulated deformable conv
// ---------------------------------------------------------------------------
__global__ __launch_bounds__(128)
void dcn_kernel(const float* __restrict__ xin,
                const float* __restrict__ w_dcn,
                const float* __restrict__ b_dcn,
                float* __restrict__ out)
{
    __shared__ float swt[CG*9*64];   // per-group slice: [c][k][o], o contiguous

    const int tx = threadIdx.x & 31;
    const int ty = threadIdx.x >> 5;
    const int x = blockIdx.x * 32 + tx;
    const int y = blockIdx.y * 4 + ty;
    const int b = blockIdx.z;

    float acc[64];
#pragma unroll
    for (int o = 0; o < 64; o++) acc[o] = 0.f;

    const float* dyp = g_scr;
    const float* dxp = g_scr + SCR_N;
    const float* mp  = g_scr + 2*SCR_N;

    for (int g = 0; g < GRP; g++) {
        __syncthreads();
        for (int idx = threadIdx.x; idx < CG*9*64; idx += 128) {
            int o = idx & 63;
            int r = idx >> 6;     // c*9 + k
            int c = r / 9, k = r % 9;
            swt[idx] = w_dcn[((size_t)o*CIN + (g*CG + c))*9 + k];
        }
        __syncthreads();

        const float* xg = xin + ((size_t)b*CIN + g*CG) * HW;

#pragma unroll 1
        for (int k = 0; k < 9; k++) {
            int oidx = ((b*GRP*KK + g*KK + k)*HH + y)*WW + x;
            float dy = dyp[oidx], dx = dxp[oidx], mv = mp[oidx];
            float py = (float)y + (float)(k/3 - 1) + dy;
            float px = (float)x + (float)(k%3 - 1) + dx;
            float fy = floorf(py), fx = floorf(px);
            int y0 = (int)fy, x0 = (int)fx;
            float ly = py - fy, lx = px - fx;

            bool vy0 = (y0   >= 0 && y0   < HH);
            bool vy1 = (y0+1 >= 0 && y0+1 < HH);
            bool vx0 = (x0   >= 0 && x0   < WW);
            bool vx1 = (x0+1 >= 0 && x0+1 < WW);
            int y0c = min(max(y0,   0), HH-1);
            int y1c = min(max(y0+1, 0), HH-1);
            int x0c = min(max(x0,   0), WW-1);
            int x1c = min(max(x0+1, 0), WW-1);

            float w00 = (1.f-ly)*(1.f-lx)*mv * ((vy0 && vx0) ? 1.f : 0.f);
            float w01 = (1.f-ly)*lx      *mv * ((vy0 && vx1) ? 1.f : 0.f);
            float w10 = ly      *(1.f-lx)*mv * ((vy1 && vx0) ? 1.f : 0.f);
            float w11 = ly      *lx      *mv * ((vy1 && vx1) ? 1.f : 0.f);

            int i00 = y0c*WW + x0c, i01 = y0c*WW + x1c;
            int i10 = y1c*WW + x0c, i11 = y1c*WW + x1c;

            float vv[CG];
#pragma unroll
            for (int c = 0; c < CG; c++) {
                const float* xc = xg + c*HW;
                vv[c] = w00*xc[i00] + w01*xc[i01] + w10*xc[i10] + w11*xc[i11];
            }
#pragma unroll
            for (int c = 0; c < CG; c++) {
                const float4* w4 = (const float4*)&swt[(c*9+k)*64];
                float v = vv[c];
#pragma unroll
                for (int q = 0; q < 16; q++) {
                    float4 w = w4[q];
                    acc[4*q+0] += w.x * v;
                    acc[4*q+1] += w.y * v;
                    acc[4*q+2] += w.z * v;
                    acc[4*q+3] += w.w * v;
                }
            }
        }
    }

#pragma unroll
    for (int o = 0; o < 64; o++)
        out[((b*64 + o)*HH + y)*WW + x] = acc[o] + b_dcn[o];
}

// ---------------------------------------------------------------------------
extern "C" void kernel_launch(void* const* d_in, const int* in_sizes, int n_in,
                              void* d_out, int out_size)
{
    const float* x     = (const float*)d_in[0];
    const float* feat  = (const float*)d_in[1];
    const float* w_off = (const float*)d_in[2];
    const float* b_off = (const float*)d_in[3];
    const float* w_dcn = (const float*)d_in[4];
    const float* b_dcn = (const float*)d_in[5];
    float* out = (float*)d_out;

    dim3 gA(WW/ATW, HH/ATH, BATCH*9);   // 5 x 20 x 36
    offset_conv_kernel<<<gA, 256>>>(feat, w_off, b_off);

    dim3 gB(WW/32, HH/4, BATCH);        // 5 x 40 x 4
    dcn_kernel<<<gB, 128>>>(x, w_dcn, b_dcn, out);
}

// round 3
// speedup vs baseline: 1.6069x; 1.6069x over previous
#include <cuda_runtime.h>
#include <math.h>
#include <cstdint>

#define BATCH 4
#define CIN   64
#define HH    160
#define WW    160
#define GRP   8
#define KK9   9
#define CG    8
#define HW    (HH*WW)

// scratch: dy, dx, mask each [B][G*9][H][W]
#define SCR_N (BATCH*GRP*KK9*HH*WW)   // 7,372,800
__device__ float g_scr[3*SCR_N];

// pre-packed tf32 B fragments: [t(72)][nt(27)][lane(32)] float2
#define NBT (72*27*32)
__device__ float2 g_bfrag[NBT];

__device__ __forceinline__ uint32_t f2tf32(float v) {
    uint32_t r;
    asm("cvt.rna.tf32.f32 %0, %1;" : "=r"(r) : "f"(v));
    return r;
}

#define MMA_TF32(d, a, b0, b1) \
    asm volatile("mma.sync.aligned.m16n8k8.row.col.f32.tf32.tf32.f32 " \
        "{%0,%1,%2,%3}, {%4,%5,%6,%7}, {%8,%9}, {%0,%1,%2,%3};" \
        : "+f"((d)[0]), "+f"((d)[1]), "+f"((d)[2]), "+f"((d)[3]) \
        : "r"((a)[0]), "r"((a)[1]), "r"((a)[2]), "r"((a)[3]), \
          "r"(b0), "r"(b1))

// ---------------------------------------------------------------------------
// Pack w_off [216][64*9] into tf32 fragment order
// ---------------------------------------------------------------------------
__global__ __launch_bounds__(256)
void pack_w_kernel(const float* __restrict__ w_off)
{
    int e = blockIdx.x * 256 + threadIdx.x;
    if (e >= NBT) return;
    int lane = e & 31;
    int r = e >> 5;
    int nt = r % 27;
    int t  = r / 27;                 // global ktile 0..71
    int n = nt * 8 + (lane >> 2);
    int k = t * 8 + (lane & 3);
    float2 v;
    v.x = __uint_as_float(f2tf32(w_off[(size_t)n * 576 + k]));
    v.y = __uint_as_float(f2tf32(w_off[(size_t)n * 576 + k + 4]));
    g_bfrag[e] = v;
}

// ---------------------------------------------------------------------------
// Kernel A: implicit-GEMM 3x3 conv via mma.sync tf32
// M=128 pixels/block (8 warps x m16), N=216 (27 n-tiles), K=576 (72 ktiles)
// ---------------------------------------------------------------------------
__device__ __forceinline__ void emit_off(int co, float v, int b, int p,
                                         const float* __restrict__ b_off) {
    v += __ldg(b_off + co);
    if (co < 144) {
        int g = co / 18, r = co % 18, k = r >> 1;
        float* dst = (r & 1) ? (g_scr + SCR_N) : g_scr;   // dx : dy
        dst[(b * GRP * KK9 + g * KK9 + k) * HW + p] = v;
    } else {
        int cm = co - 144, g = cm / 9, k = cm % 9;
        g_scr[2 * SCR_N + (b * GRP * KK9 + g * KK9 + k) * HW + p] =
            1.f / (1.f + expf(-v));
    }
}

__global__ __launch_bounds__(256)
void offset_conv_mma(const float* __restrict__ feat,
                     const float* __restrict__ b_off)
{
    const int tid  = threadIdx.x;
    const int warp = tid >> 5, lane = tid & 31;
    const int b  = blockIdx.y;
    const int p0 = blockIdx.x * 128;

    const int m0 = warp * 16 + (lane >> 2);
    const int pA = p0 + m0, pB = pA + 8;
    const int yA = pA / WW, xA = pA % WW;
    const int yB = pB / WW, xB = pB % WW;
    const float* fb = feat + (size_t)b * CIN * HW;

    float acc[27][4];
#pragma unroll
    for (int i = 0; i < 27; i++)
#pragma unroll
        for (int j = 0; j < 4; j++) acc[i][j] = 0.f;

    const int c = lane & 3;
    int ci0 = 0, kk0 = c;        // k-sequence: c, c+8, c+16, ...
    int ci1 = 0, kk1 = c + 4;    // k-sequence: c+4, c+12, ...

    // sample pair for (ci, kk): rows pA, pB
    auto samp2 = [&](int ci, int kk, float& vA, float& vB) {
        int dy = (kk > 5) ? 2 : ((kk > 2) ? 1 : 0);
        int dx = kk - dy * 3;
        int base = ci * HW;
        int gyA = yA + dy - 1, gxA = xA + dx - 1;
        int gyB = yB + dy - 1, gxB = xB + dx - 1;
        vA = ((unsigned)gyA < HH && (unsigned)gxA < WW)
               ? __ldg(fb + base + gyA * WW + gxA) : 0.f;
        vB = ((unsigned)gyB < HH && (unsigned)gxB < WW)
               ? __ldg(fb + base + gyB * WW + gxB) : 0.f;
    };

    uint32_t a[4];
    {
        float v0, v1, v2, v3;
        samp2(ci0, kk0, v0, v1);
        samp2(ci1, kk1, v2, v3);
        a[0] = f2tf32(v0); a[1] = f2tf32(v1);
        a[2] = f2tf32(v2); a[3] = f2tf32(v3);
    }

    const float2* bp = g_bfrag + lane;

#pragma unroll 1
    for (int t = 0; t < 72; t++) {
        // prefetch next ktile's A fragment (issued before the MMA chain)
        uint32_t an[4] = {0u, 0u, 0u, 0u};
        if (t < 71) {
            if (kk0 == 0) kk0 = 8; else { kk0--; ci0++; }
            if (kk1 == 0) kk1 = 8; else { kk1--; ci1++; }
            float v0, v1, v2, v3;
            samp2(ci0, kk0, v0, v1);
            samp2(ci1, kk1, v2, v3);
            an[0] = f2tf32(v0); an[1] = f2tf32(v1);
            an[2] = f2tf32(v2); an[3] = f2tf32(v3);
        }

        const float2* bt = bp + (size_t)t * 27 * 32;
#pragma unroll
        for (int nt = 0; nt < 27; nt++) {
            float2 bb = __ldg(bt + nt * 32);
            MMA_TF32(acc[nt], a, __float_as_uint(bb.x), __float_as_uint(bb.y));
        }

        a[0] = an[0]; a[1] = an[1]; a[2] = an[2]; a[3] = an[3];
    }

    // epilogue: c0,c1 -> row pA cols 2c,2c+1 ; c2,c3 -> row pB
#pragma unroll
    for (int nt = 0; nt < 27; nt++) {
#pragma unroll
        for (int i = 0; i < 4; i++) {
            int p  = (i >= 2) ? pB : pA;
            int co = nt * 8 + (lane & 3) * 2 + (i & 1);
            emit_off(co, acc[nt][i], b, p, b_off);
        }
    }
}

// ---------------------------------------------------------------------------
// Kernel B: modulated deformable conv (unchanged, known-good)
// ---------------------------------------------------------------------------
__global__ __launch_bounds__(128)
void dcn_kernel(const float* __restrict__ xin,
                const float* __restrict__ w_dcn,
                const float* __restrict__ b_dcn,
                float* __restrict__ out)
{
    __shared__ float swt[CG*9*64];

    const int tx = threadIdx.x & 31;
    const int ty = threadIdx.x >> 5;
    const int x = blockIdx.x * 32 + tx;
    const int y = blockIdx.y * 4 + ty;
    const int b = blockIdx.z;

    float acc[64];
#pragma unroll
    for (int o = 0; o < 64; o++) acc[o] = 0.f;

    const float* dyp = g_scr;
    const float* dxp = g_scr + SCR_N;
    const float* mp  = g_scr + 2*SCR_N;

    for (int g = 0; g < GRP; g++) {
        __syncthreads();
        for (int idx = threadIdx.x; idx < CG*9*64; idx += 128) {
            int o = idx & 63;
            int r = idx >> 6;
            int c = r / 9, k = r % 9;
            swt[idx] = w_dcn[((size_t)o*CIN + (g*CG + c))*9 + k];
        }
        __syncthreads();

        const float* xg = xin + ((size_t)b*CIN + g*CG) * HW;

#pragma unroll 1
        for (int k = 0; k < 9; k++) {
            int oidx = ((b*GRP*KK9 + g*KK9 + k)*HH + y)*WW + x;
            float dy = dyp[oidx], dx = dxp[oidx], mv = mp[oidx];
            float py = (float)y + (float)(k/3 - 1) + dy;
            float px = (float)x + (float)(k%3 - 1) + dx;
            float fy = floorf(py), fx = floorf(px);
            int y0 = (int)fy, x0 = (int)fx;
            float ly = py - fy, lx = px - fx;

            bool vy0 = (y0   >= 0 && y0   < HH);
            bool vy1 = (y0+1 >= 0 && y0+1 < HH);
            bool vx0 = (x0   >= 0 && x0   < WW);
            bool vx1 = (x0+1 >= 0 && x0+1 < WW);
            int y0c = min(max(y0,   0), HH-1);
            int y1c = min(max(y0+1, 0), HH-1);
            int x0c = min(max(x0,   0), WW-1);
            int x1c = min(max(x0+1, 0), WW-1);

            float w00 = (1.f-ly)*(1.f-lx)*mv * ((vy0 && vx0) ? 1.f : 0.f);
            float w01 = (1.f-ly)*lx      *mv * ((vy0 && vx1) ? 1.f : 0.f);
            float w10 = ly      *(1.f-lx)*mv * ((vy1 && vx0) ? 1.f : 0.f);
            float w11 = ly      *lx      *mv * ((vy1 && vx1) ? 1.f : 0.f);

            int i00 = y0c*WW + x0c, i01 = y0c*WW + x1c;
            int i10 = y1c*WW + x0c, i11 = y1c*WW + x1c;

            float vv[CG];
#pragma unroll
            for (int c = 0; c < CG; c++) {
                const float* xc = xg + c*HW;
                vv[c] = w00*xc[i00] + w01*xc[i01] + w10*xc[i10] + w11*xc[i11];
            }
#pragma unroll
            for (int c = 0; c < CG; c++) {
                const float4* w4 = (const float4*)&swt[(c*9+k)*64];
                float v = vv[c];
#pragma unroll
                for (int q = 0; q < 16; q++) {
                    float4 w = w4[q];
                    acc[4*q+0] += w.x * v;
                    acc[4*q+1] += w.y * v;
                    acc[4*q+2] += w.z * v;
                    acc[4*q+3] += w.w * v;
                }
            }
        }
    }

#pragma unroll
    for (int o = 0; o < 64; o++)
        out[((b*64 + o)*HH + y)*WW + x] = acc[o] + b_dcn[o];
}

// ---------------------------------------------------------------------------
extern "C" void kernel_launch(void* const* d_in, const int* in_sizes, int n_in,
                              void* d_out, int out_size)
{
    const float* x     = (const float*)d_in[0];
    const float* feat  = (const float*)d_in[1];
    const float* w_off = (const float*)d_in[2];
    const float* b_off = (const float*)d_in[3];
    const float* w_dcn = (const float*)d_in[4];
    const float* b_dcn = (const float*)d_in[5];
    float* out = (float*)d_out;

    pack_w_kernel<<<(NBT + 255) / 256, 256>>>(w_off);

    dim3 gA(HW / 128, BATCH);           // 200 x 4
    offset_conv_mma<<<gA, 256>>>(feat, b_off);

    dim3 gB(WW/32, HH/4, BATCH);        // 5 x 40 x 4
    dcn_kernel<<<gB, 128>>>(x, w_dcn, b_dcn, out);
}